// round 1
// baseline (speedup 1.0000x reference)
#include <cuda_runtime.h>
#include <math.h>

// Problem constants
constexpr int Bv = 8;
constexpr int Tv = 2048;
constexpr int Dv = 512;
constexpr int Hv = 2048;
constexpr int BT = Bv * Tv;            // 16384
constexpr int TD = Tv * Dv;            // 1048576
constexpr int BTD = Bv * Tv * Dv;      // 8388608
constexpr int N2D = Bv * 2 * Dv;       // 8192 (U / C column count)

// ---------------- scratch (device globals; no allocation allowed) ----------
__device__ float g_h   [BTD];          // LN1 output
__device__ float g_K   [BTD];
__device__ float g_V   [BTD];
__device__ float g_Q   [BTD];
__device__ float g_Kmax[TD];
__device__ float g_expw[Tv * Tv];
__device__ float g_U   [Tv * N2D];     // [s, b*1024 + (d | 512+d)] = expK | expK*V
__device__ float g_C   [Tv * N2D];     // einsum result: den | num
__device__ float g_Y   [BTD];          // gated attention
__device__ float g_out [BTD];          // attn + x (residual 1)
__device__ float g_h2  [BTD];          // LN2 output
__device__ float g_a1  [BT * Hv];      // MLP hidden (16384 x 2048)

// ---------------- LayerNorm: one block (256 thr) per row of 512 ------------
__global__ void ln_kernel(const float* __restrict__ x,
                          const float* __restrict__ g,
                          const float* __restrict__ b,
                          float* __restrict__ y) {
    const int row = blockIdx.x;
    const float* xr = x + (size_t)row * Dv;
    const int t = threadIdx.x;
    float v0 = xr[t];
    float v1 = xr[t + 256];
    float s  = v0 + v1;
    float sq = v0 * v0 + v1 * v1;
    #pragma unroll
    for (int off = 16; off > 0; off >>= 1) {
        s  += __shfl_down_sync(0xffffffffu, s,  off);
        sq += __shfl_down_sync(0xffffffffu, sq, off);
    }
    __shared__ float ssum[8], ssq[8];
    __shared__ float s_mu, s_rstd;
    const int wid = t >> 5, lane = t & 31;
    if (lane == 0) { ssum[wid] = s; ssq[wid] = sq; }
    __syncthreads();
    if (t == 0) {
        float ts = 0.f, tq = 0.f;
        #pragma unroll
        for (int i = 0; i < 8; i++) { ts += ssum[i]; tq += ssq[i]; }
        float mu  = ts * (1.0f / Dv);
        float var = tq * (1.0f / Dv) - mu * mu;
        s_mu = mu;
        s_rstd = rsqrtf(var + 1e-5f);
    }
    __syncthreads();
    float* yr = y + (size_t)row * Dv;
    yr[t]       = (v0 - s_mu) * s_rstd * g[t]       + b[t];
    yr[t + 256] = (v1 - s_mu) * s_rstd * g[t + 256] + b[t + 256];
}

// ---------------- exp_w: row-max-stabilized exp of w[T,T] ------------------
__global__ void expw_kernel(const float* __restrict__ w, float* __restrict__ ew) {
    const int row = blockIdx.x;
    const float* wr = w + (size_t)row * Tv;
    const int t = threadIdx.x;
    float v[8];
    float m = -1e30f;
    #pragma unroll
    for (int i = 0; i < 8; i++) {
        v[i] = wr[t + i * 256];
        m = fmaxf(m, v[i]);
    }
    #pragma unroll
    for (int off = 16; off > 0; off >>= 1)
        m = fmaxf(m, __shfl_down_sync(0xffffffffu, m, off));
    __shared__ float sm[8];
    __shared__ float s_max;
    const int wid = t >> 5, lane = t & 31;
    if (lane == 0) sm[wid] = m;
    __syncthreads();
    if (t == 0) {
        float mm = sm[0];
        #pragma unroll
        for (int i = 1; i < 8; i++) mm = fmaxf(mm, sm[i]);
        s_max = mm;
    }
    __syncthreads();
    float* er = ew + (size_t)row * Tv;
    #pragma unroll
    for (int i = 0; i < 8; i++)
        er[t + i * 256] = expf(v[i] - s_max);
}

// ---------------- K column-max over batch dim -------------------------------
__global__ void kmax_kernel(const float* __restrict__ K, float* __restrict__ Kmax) {
    const int idx = blockIdx.x * blockDim.x + threadIdx.x;
    if (idx >= TD) return;
    float m = K[idx];
    #pragma unroll
    for (int b = 1; b < Bv; b++)
        m = fmaxf(m, K[(size_t)b * TD + idx]);
    Kmax[idx] = m;
}

// ---------------- build U: [s, b*1024+d]=expK, [s, b*1024+512+d]=expK*V -----
__global__ void buildU_kernel(const float* __restrict__ K,
                              const float* __restrict__ V,
                              const float* __restrict__ Kmax,
                              float* __restrict__ U) {
    const int idx = blockIdx.x * blockDim.x + threadIdx.x;
    if (idx >= BTD) return;
    const int b   = idx / TD;
    const int rem = idx - b * TD;          // s*D + d
    const int s   = rem >> 9;              // /512
    const int d   = rem & 511;
    float e = expf(K[idx] - Kmax[rem]);
    size_t base = (size_t)s * N2D + b * 1024 + d;
    U[base]       = e;
    U[base + 512] = e * V[idx];
}

// ---------------- gate: Y = sigmoid(Q) * num / den --------------------------
__global__ void gate_kernel(const float* __restrict__ Q,
                            const float* __restrict__ C,
                            float* __restrict__ Y) {
    const int idx = blockIdx.x * blockDim.x + threadIdx.x;
    if (idx >= BTD) return;
    const int b   = idx / TD;
    const int rem = idx - b * TD;
    const int t   = rem >> 9;
    const int d   = rem & 511;
    size_t base = (size_t)t * N2D + b * 1024 + d;
    float den = C[base];
    float num = C[base + 512];
    float q = Q[idx];
    float sig = 1.0f / (1.0f + expf(-q));
    Y[idx] = sig * num / den;
}

// ---------------- SGEMM: C = epi(A@B + bias [+ res]) ------------------------
// A [M,K] row-major, B [K,N] row-major, C [M,N] row-major.
// 128x128 block tile, BK=16, 256 threads, 8x8 per thread.
// EPI: 0=none, 1=+bias, 2=+bias+res, 3=gelu(+bias), 4=gelu(+bias)+res
__device__ __forceinline__ float gelu_exact(float v) {
    return 0.5f * v * (1.0f + erff(v * 0.70710678118654752f));
}

template <int EPI>
__global__ __launch_bounds__(256)
void sgemm_kernel(const float* __restrict__ A, const float* __restrict__ B,
                  const float* __restrict__ bias, const float* __restrict__ res,
                  float* __restrict__ C, int M, int N, int K) {
    __shared__ float As[16][128];
    __shared__ float Bs[16][128];
    const int tid = threadIdx.x;
    const int bM = blockIdx.y * 128;
    const int bN = blockIdx.x * 128;
    const int tr = (tid >> 4) << 3;   // (tid/16)*8
    const int tc = (tid & 15) << 3;   // (tid%16)*8

    const int arow = tid >> 2;            // 0..63
    const int acol = (tid & 3) << 2;      // 0,4,8,12
    const int brow = tid >> 5;            // 0..7
    const int bcol = (tid & 31) << 2;     // 0..124

    float acc[8][8] = {};

    for (int k0 = 0; k0 < K; k0 += 16) {
        #pragma unroll
        for (int i = 0; i < 2; i++) {
            int r = arow + i * 64;
            float4 v = *(const float4*)(A + (size_t)(bM + r) * K + k0 + acol);
            As[acol + 0][r] = v.x;
            As[acol + 1][r] = v.y;
            As[acol + 2][r] = v.z;
            As[acol + 3][r] = v.w;
        }
        #pragma unroll
        for (int i = 0; i < 2; i++) {
            int r = brow + i * 8;
            *(float4*)(&Bs[r][bcol]) =
                *(const float4*)(B + (size_t)(k0 + r) * N + bN + bcol);
        }
        __syncthreads();
        #pragma unroll
        for (int k = 0; k < 16; k++) {
            float ra[8], rb[8];
            #pragma unroll
            for (int i = 0; i < 8; i++) ra[i] = As[k][tr + i];
            #pragma unroll
            for (int j = 0; j < 8; j++) rb[j] = Bs[k][tc + j];
            #pragma unroll
            for (int i = 0; i < 8; i++)
                #pragma unroll
                for (int j = 0; j < 8; j++)
                    acc[i][j] = fmaf(ra[i], rb[j], acc[i][j]);
        }
        __syncthreads();
    }

    #pragma unroll
    for (int i = 0; i < 8; i++) {
        size_t row = (size_t)(bM + tr + i);
        #pragma unroll
        for (int j = 0; j < 8; j++) {
            int col = bN + tc + j;
            float v = acc[i][j];
            if (EPI >= 1) v += bias[col];
            if (EPI == 3 || EPI == 4) v = gelu_exact(v);
            if (EPI == 2 || EPI == 4) v += res[row * N + col];
            C[row * N + col] = v;
        }
    }
}

// ---------------- launch ----------------------------------------------------
extern "C" void kernel_launch(void* const* d_in, const int* in_sizes, int n_in,
                              void* d_out, int out_size) {
    const float* x     = (const float*)d_in[0];
    const float* ln1_g = (const float*)d_in[1];
    const float* ln1_b = (const float*)d_in[2];
    const float* Wk    = (const float*)d_in[3];
    const float* bk    = (const float*)d_in[4];
    const float* Wv    = (const float*)d_in[5];
    const float* bv    = (const float*)d_in[6];
    const float* Wq    = (const float*)d_in[7];
    const float* bq    = (const float*)d_in[8];
    const float* w     = (const float*)d_in[9];
    const float* Wo    = (const float*)d_in[10];
    const float* bo    = (const float*)d_in[11];
    const float* ln2_g = (const float*)d_in[12];
    const float* ln2_b = (const float*)d_in[13];
    const float* W1    = (const float*)d_in[14];
    const float* b1    = (const float*)d_in[15];
    const float* W2    = (const float*)d_in[16];
    const float* b2    = (const float*)d_in[17];
    float* out = (float*)d_out;

    float *p_h, *p_K, *p_V, *p_Q, *p_Kmax, *p_expw, *p_U, *p_C, *p_Y,
          *p_out, *p_h2, *p_a1;
    cudaGetSymbolAddress((void**)&p_h,    g_h);
    cudaGetSymbolAddress((void**)&p_K,    g_K);
    cudaGetSymbolAddress((void**)&p_V,    g_V);
    cudaGetSymbolAddress((void**)&p_Q,    g_Q);
    cudaGetSymbolAddress((void**)&p_Kmax, g_Kmax);
    cudaGetSymbolAddress((void**)&p_expw, g_expw);
    cudaGetSymbolAddress((void**)&p_U,    g_U);
    cudaGetSymbolAddress((void**)&p_C,    g_C);
    cudaGetSymbolAddress((void**)&p_Y,    g_Y);
    cudaGetSymbolAddress((void**)&p_out,  g_out);
    cudaGetSymbolAddress((void**)&p_h2,   g_h2);
    cudaGetSymbolAddress((void**)&p_a1,   g_a1);

    // 1. LN1
    ln_kernel<<<BT, 256>>>(x, ln1_g, ln1_b, p_h);

    // 2-4. K, V, Q projections: [16384,512] @ [512,512] + bias
    {
        dim3 grid(Dv / 128, BT / 128);
        sgemm_kernel<1><<<grid, 256>>>(p_h, Wk, bk, nullptr, p_K, BT, Dv, Dv);
        sgemm_kernel<1><<<grid, 256>>>(p_h, Wv, bv, nullptr, p_V, BT, Dv, Dv);
        sgemm_kernel<1><<<grid, 256>>>(p_h, Wq, bq, nullptr, p_Q, BT, Dv, Dv);
    }

    // 5. batch-max of K
    kmax_kernel<<<(TD + 255) / 256, 256>>>(p_K, p_Kmax);

    // 6. exp_w (row-max stabilized)
    expw_kernel<<<Tv, 256>>>(w, p_expw);

    // 7. build U = [expK | expK*V] in [T, B*2D] layout
    buildU_kernel<<<(BTD + 255) / 256, 256>>>(p_K, p_V, p_Kmax, p_U);

    // 8. AFT core GEMM: C[T, 8192] = exp_w[T,T] @ U[T, 8192]
    {
        dim3 grid(N2D / 128, Tv / 128);
        sgemm_kernel<0><<<grid, 256>>>(p_expw, p_U, nullptr, nullptr, p_C,
                                       Tv, N2D, Tv);
    }

    // 9. gate: Y = sigmoid(Q) * num / den
    gate_kernel<<<(BTD + 255) / 256, 256>>>(p_Q, p_C, p_Y);

    // 10. out = Y @ Wo + bo + x (residual)
    {
        dim3 grid(Dv / 128, BT / 128);
        sgemm_kernel<2><<<grid, 256>>>(p_Y, Wo, bo, x, p_out, BT, Dv, Dv);
    }

    // 11. LN2
    ln_kernel<<<BT, 256>>>(p_out, ln2_g, ln2_b, p_h2);

    // 12. a1 = gelu(h2 @ W1 + b1)  [16384, 2048]
    {
        dim3 grid(Hv / 128, BT / 128);
        sgemm_kernel<3><<<grid, 256>>>(p_h2, W1, b1, nullptr, p_a1, BT, Hv, Dv);
    }

    // 13. out = gelu(a1 @ W2 + b2) + out_residual
    {
        dim3 grid(Dv / 128, BT / 128);
        sgemm_kernel<4><<<grid, 256>>>(p_a1, W2, b2, p_out, out, BT, Dv, Hv);
    }
}

// round 2
// speedup vs baseline: 3.2530x; 3.2530x over previous
#include <cuda_runtime.h>
#include <math.h>
#include <stdint.h>

// Problem constants
constexpr int Bv = 8;
constexpr int Tv = 2048;
constexpr int Dv = 512;
constexpr int Hv = 2048;
constexpr int BT = Bv * Tv;            // 16384
constexpr int TD = Tv * Dv;            // 1048576
constexpr int BTD = Bv * Tv * Dv;      // 8388608
constexpr int N2D = Bv * 2 * Dv;       // 8192

// ---------------- scratch (device globals; no allocation allowed) ----------
__device__ float g_h   [BTD];
__device__ float g_K   [BTD];
__device__ float g_V   [BTD];
__device__ float g_Q   [BTD];
__device__ float g_Kmax[TD];
__device__ float g_expw[Tv * Tv];
__device__ float g_U   [Tv * N2D];
__device__ float g_C   [Tv * N2D];
__device__ float g_Y   [BTD];
__device__ float g_out [BTD];
__device__ float g_h2  [BTD];
__device__ float g_a1  [BT * Hv];

// ---------------- LayerNorm ----------------
__global__ void ln_kernel(const float* __restrict__ x,
                          const float* __restrict__ g,
                          const float* __restrict__ b,
                          float* __restrict__ y) {
    const int row = blockIdx.x;
    const float* xr = x + (size_t)row * Dv;
    const int t = threadIdx.x;
    float v0 = xr[t];
    float v1 = xr[t + 256];
    float s  = v0 + v1;
    float sq = v0 * v0 + v1 * v1;
    #pragma unroll
    for (int off = 16; off > 0; off >>= 1) {
        s  += __shfl_down_sync(0xffffffffu, s,  off);
        sq += __shfl_down_sync(0xffffffffu, sq, off);
    }
    __shared__ float ssum[8], ssq[8];
    __shared__ float s_mu, s_rstd;
    const int wid = t >> 5, lane = t & 31;
    if (lane == 0) { ssum[wid] = s; ssq[wid] = sq; }
    __syncthreads();
    if (t == 0) {
        float ts = 0.f, tq = 0.f;
        #pragma unroll
        for (int i = 0; i < 8; i++) { ts += ssum[i]; tq += ssq[i]; }
        float mu  = ts * (1.0f / Dv);
        float var = tq * (1.0f / Dv) - mu * mu;
        s_mu = mu;
        s_rstd = rsqrtf(var + 1e-5f);
    }
    __syncthreads();
    float* yr = y + (size_t)row * Dv;
    yr[t]       = (v0 - s_mu) * s_rstd * g[t]       + b[t];
    yr[t + 256] = (v1 - s_mu) * s_rstd * g[t + 256] + b[t + 256];
}

// ---------------- exp_w ----------------
__global__ void expw_kernel(const float* __restrict__ w, float* __restrict__ ew) {
    const int row = blockIdx.x;
    const float* wr = w + (size_t)row * Tv;
    const int t = threadIdx.x;
    float v[8];
    float m = -1e30f;
    #pragma unroll
    for (int i = 0; i < 8; i++) {
        v[i] = wr[t + i * 256];
        m = fmaxf(m, v[i]);
    }
    #pragma unroll
    for (int off = 16; off > 0; off >>= 1)
        m = fmaxf(m, __shfl_down_sync(0xffffffffu, m, off));
    __shared__ float sm[8];
    __shared__ float s_max;
    const int wid = t >> 5, lane = t & 31;
    if (lane == 0) sm[wid] = m;
    __syncthreads();
    if (t == 0) {
        float mm = sm[0];
        #pragma unroll
        for (int i = 1; i < 8; i++) mm = fmaxf(mm, sm[i]);
        s_max = mm;
    }
    __syncthreads();
    float* er = ew + (size_t)row * Tv;
    #pragma unroll
    for (int i = 0; i < 8; i++)
        er[t + i * 256] = expf(v[i] - s_max);
}

// ---------------- K batch-max ----------------
__global__ void kmax_kernel(const float* __restrict__ K, float* __restrict__ Kmax) {
    const int idx = blockIdx.x * blockDim.x + threadIdx.x;
    if (idx >= TD) return;
    float m = K[idx];
    #pragma unroll
    for (int b = 1; b < Bv; b++)
        m = fmaxf(m, K[(size_t)b * TD + idx]);
    Kmax[idx] = m;
}

// ---------------- build U ----------------
__global__ void buildU_kernel(const float* __restrict__ K,
                              const float* __restrict__ V,
                              const float* __restrict__ Kmax,
                              float* __restrict__ U) {
    const int idx = blockIdx.x * blockDim.x + threadIdx.x;
    if (idx >= BTD) return;
    const int b   = idx / TD;
    const int rem = idx - b * TD;
    const int s   = rem >> 9;
    const int d   = rem & 511;
    float e = expf(K[idx] - Kmax[rem]);
    size_t base = (size_t)s * N2D + b * 1024 + d;
    U[base]       = e;
    U[base + 512] = e * V[idx];
}

// ---------------- gate ----------------
__global__ void gate_kernel(const float* __restrict__ Q,
                            const float* __restrict__ C,
                            float* __restrict__ Y) {
    const int idx = blockIdx.x * blockDim.x + threadIdx.x;
    if (idx >= BTD) return;
    const int b   = idx / TD;
    const int rem = idx - b * TD;
    const int t   = rem >> 9;
    const int d   = rem & 511;
    size_t base = (size_t)t * N2D + b * 1024 + d;
    float den = C[base];
    float num = C[base + 512];
    float q = Q[idx];
    float sig = 1.0f / (1.0f + expf(-q));
    Y[idx] = sig * num / den;
}

// ============================================================================
// TF32 tensor-core GEMM: C = epi(A@B + bias [+ res])
// A [M,K] rm, B [K,N] rm, C [M,N] rm. 128x128x32 tile, 256 thr, 2-stage cp.async
// ============================================================================
__device__ __forceinline__ float gelu_exact(float v) {
    return 0.5f * v * (1.0f + erff(v * 0.70710678118654752f));
}

__device__ __forceinline__ void cp_async16(float* dst, const float* src) {
    uint32_t d = (uint32_t)__cvta_generic_to_shared(dst);
    asm volatile("cp.async.cg.shared.global [%0], [%1], 16;\n" :: "r"(d), "l"(src));
}
__device__ __forceinline__ uint32_t f2tf(float f) {
    uint32_t r;
    asm("cvt.rna.tf32.f32 %0, %1;\n" : "=r"(r) : "f"(f));
    return r;
}
__device__ __forceinline__ void mma_tf32(float* c, const uint32_t* a, const uint32_t* b) {
    asm volatile(
        "mma.sync.aligned.m16n8k8.row.col.f32.tf32.tf32.f32 "
        "{%0,%1,%2,%3}, {%4,%5,%6,%7}, {%8,%9}, {%0,%1,%2,%3};\n"
        : "+f"(c[0]), "+f"(c[1]), "+f"(c[2]), "+f"(c[3])
        : "r"(a[0]), "r"(a[1]), "r"(a[2]), "r"(a[3]), "r"(b[0]), "r"(b[1]));
}

constexpr int BK = 32;
constexpr int AS_STRIDE = 36;                 // conflict-free A frag loads
constexpr int BS_STRIDE = 136;                // conflict-free B frag loads
constexpr int AS_FLOATS = 128 * AS_STRIDE;    // 4608
constexpr int BS_FLOATS = BK * BS_STRIDE;     // 4352
constexpr int STAGE_FLOATS = AS_FLOATS + BS_FLOATS;   // 8960
constexpr int SMEM_BYTES = 2 * STAGE_FLOATS * 4;      // 71680

// EPI: 0=none, 1=+bias, 2=+bias+res, 3=gelu(+bias), 4=gelu(+bias)+res
template <int EPI>
__global__ __launch_bounds__(256, 2)
void tgemm_kernel(const float* __restrict__ A, const float* __restrict__ B,
                  const float* __restrict__ bias, const float* __restrict__ res,
                  float* __restrict__ C, int M, int N, int K) {
    extern __shared__ float smem[];
    const int tid  = threadIdx.x;
    const int lane = tid & 31;
    const int warp = tid >> 5;
    const int wrow = warp & 1;    // 2 warp rows of 64
    const int wcol = warp >> 1;   // 4 warp cols of 32
    const int bM = blockIdx.y * 128;
    const int bN = blockIdx.x * 128;

    float c[4][4][4];
    #pragma unroll
    for (int i = 0; i < 4; i++)
        #pragma unroll
        for (int j = 0; j < 4; j++)
            #pragma unroll
            for (int k = 0; k < 4; k++) c[i][j][k] = 0.f;

    const int nk = K / BK;

    // stage loader
    auto load_stage = [&](int kt, int s) {
        float* As = smem + s * STAGE_FLOATS;
        float* Bs = As + AS_FLOATS;
        const float* Ag = A + (size_t)bM * K + kt * BK;
        const float* Bg = B + (size_t)(kt * BK) * N + bN;
        #pragma unroll
        for (int i = 0; i < 4; i++) {
            int ch = i * 256 + tid;               // 1024 chunks of 16B
            int r  = ch >> 3;
            int cc = (ch & 7) * 4;
            cp_async16(As + r * AS_STRIDE + cc, Ag + (size_t)r * K + cc);
        }
        #pragma unroll
        for (int i = 0; i < 4; i++) {
            int ch = i * 256 + tid;
            int r  = ch >> 5;
            int cc = (ch & 31) * 4;
            cp_async16(Bs + r * BS_STRIDE + cc, Bg + (size_t)r * N + cc);
        }
        asm volatile("cp.async.commit_group;\n");
    };

    load_stage(0, 0);

    for (int kt = 0; kt < nk; kt++) {
        const int s = kt & 1;
        if (kt + 1 < nk) {
            load_stage(kt + 1, s ^ 1);
            asm volatile("cp.async.wait_group 1;\n");
        } else {
            asm volatile("cp.async.wait_group 0;\n");
        }
        __syncthreads();

        const float* As = smem + s * STAGE_FLOATS;
        const float* Bs = As + AS_FLOATS;

        #pragma unroll
        for (int ks = 0; ks < 4; ks++) {
            const int k = ks * 8 + (lane & 3);
            uint32_t a[4][4];
            #pragma unroll
            for (int mt = 0; mt < 4; mt++) {
                const int m = wrow * 64 + mt * 16 + (lane >> 2);
                a[mt][0] = f2tf(As[m * AS_STRIDE + k]);
                a[mt][1] = f2tf(As[(m + 8) * AS_STRIDE + k]);
                a[mt][2] = f2tf(As[m * AS_STRIDE + k + 4]);
                a[mt][3] = f2tf(As[(m + 8) * AS_STRIDE + k + 4]);
            }
            uint32_t b[4][2];
            #pragma unroll
            for (int nt = 0; nt < 4; nt++) {
                const int n = wcol * 32 + nt * 8 + (lane >> 2);
                b[nt][0] = f2tf(Bs[k * BS_STRIDE + n]);
                b[nt][1] = f2tf(Bs[(k + 4) * BS_STRIDE + n]);
            }
            #pragma unroll
            for (int mt = 0; mt < 4; mt++)
                #pragma unroll
                for (int nt = 0; nt < 4; nt++)
                    mma_tf32(c[mt][nt], a[mt], b[nt]);
        }
        __syncthreads();
    }

    // epilogue
    #pragma unroll
    for (int mt = 0; mt < 4; mt++) {
        #pragma unroll
        for (int nt = 0; nt < 4; nt++) {
            const int row0 = bM + wrow * 64 + mt * 16 + (lane >> 2);
            const int col  = bN + wcol * 32 + nt * 8 + (lane & 3) * 2;
            #pragma unroll
            for (int h = 0; h < 2; h++) {
                const size_t row = row0 + h * 8;
                float v0 = c[mt][nt][h * 2 + 0];
                float v1 = c[mt][nt][h * 2 + 1];
                if (EPI >= 1) { v0 += bias[col]; v1 += bias[col + 1]; }
                if (EPI == 3 || EPI == 4) { v0 = gelu_exact(v0); v1 = gelu_exact(v1); }
                if (EPI == 2 || EPI == 4) {
                    v0 += res[row * N + col];
                    v1 += res[row * N + col + 1];
                }
                *(float2*)(C + row * N + col) = make_float2(v0, v1);
            }
        }
    }
}

// ---------------- launch ----------------
extern "C" void kernel_launch(void* const* d_in, const int* in_sizes, int n_in,
                              void* d_out, int out_size) {
    const float* x     = (const float*)d_in[0];
    const float* ln1_g = (const float*)d_in[1];
    const float* ln1_b = (const float*)d_in[2];
    const float* Wk    = (const float*)d_in[3];
    const float* bk    = (const float*)d_in[4];
    const float* Wv    = (const float*)d_in[5];
    const float* bv    = (const float*)d_in[6];
    const float* Wq    = (const float*)d_in[7];
    const float* bq    = (const float*)d_in[8];
    const float* w     = (const float*)d_in[9];
    const float* Wo    = (const float*)d_in[10];
    const float* bo    = (const float*)d_in[11];
    const float* ln2_g = (const float*)d_in[12];
    const float* ln2_b = (const float*)d_in[13];
    const float* W1    = (const float*)d_in[14];
    const float* b1    = (const float*)d_in[15];
    const float* W2    = (const float*)d_in[16];
    const float* b2    = (const float*)d_in[17];
    float* out = (float*)d_out;

    float *p_h, *p_K, *p_V, *p_Q, *p_Kmax, *p_expw, *p_U, *p_C, *p_Y,
          *p_out, *p_h2, *p_a1;
    cudaGetSymbolAddress((void**)&p_h,    g_h);
    cudaGetSymbolAddress((void**)&p_K,    g_K);
    cudaGetSymbolAddress((void**)&p_V,    g_V);
    cudaGetSymbolAddress((void**)&p_Q,    g_Q);
    cudaGetSymbolAddress((void**)&p_Kmax, g_Kmax);
    cudaGetSymbolAddress((void**)&p_expw, g_expw);
    cudaGetSymbolAddress((void**)&p_U,    g_U);
    cudaGetSymbolAddress((void**)&p_C,    g_C);
    cudaGetSymbolAddress((void**)&p_Y,    g_Y);
    cudaGetSymbolAddress((void**)&p_out,  g_out);
    cudaGetSymbolAddress((void**)&p_h2,   g_h2);
    cudaGetSymbolAddress((void**)&p_a1,   g_a1);

    cudaFuncSetAttribute(tgemm_kernel<0>, cudaFuncAttributeMaxDynamicSharedMemorySize, SMEM_BYTES);
    cudaFuncSetAttribute(tgemm_kernel<1>, cudaFuncAttributeMaxDynamicSharedMemorySize, SMEM_BYTES);
    cudaFuncSetAttribute(tgemm_kernel<2>, cudaFuncAttributeMaxDynamicSharedMemorySize, SMEM_BYTES);
    cudaFuncSetAttribute(tgemm_kernel<3>, cudaFuncAttributeMaxDynamicSharedMemorySize, SMEM_BYTES);
    cudaFuncSetAttribute(tgemm_kernel<4>, cudaFuncAttributeMaxDynamicSharedMemorySize, SMEM_BYTES);

    // 1. LN1
    ln_kernel<<<BT, 256>>>(x, ln1_g, ln1_b, p_h);

    // 2-4. K, V, Q projections
    {
        dim3 grid(Dv / 128, BT / 128);
        tgemm_kernel<1><<<grid, 256, SMEM_BYTES>>>(p_h, Wk, bk, nullptr, p_K, BT, Dv, Dv);
        tgemm_kernel<1><<<grid, 256, SMEM_BYTES>>>(p_h, Wv, bv, nullptr, p_V, BT, Dv, Dv);
        tgemm_kernel<1><<<grid, 256, SMEM_BYTES>>>(p_h, Wq, bq, nullptr, p_Q, BT, Dv, Dv);
    }

    // 5. batch-max of K
    kmax_kernel<<<(TD + 255) / 256, 256>>>(p_K, p_Kmax);

    // 6. exp_w
    expw_kernel<<<Tv, 256>>>(w, p_expw);

    // 7. build U
    buildU_kernel<<<(BTD + 255) / 256, 256>>>(p_K, p_V, p_Kmax, p_U);

    // 8. AFT core GEMM: C[T, 8192] = exp_w[T,T] @ U[T, 8192]
    {
        dim3 grid(N2D / 128, Tv / 128);
        tgemm_kernel<0><<<grid, 256, SMEM_BYTES>>>(p_expw, p_U, nullptr, nullptr, p_C, Tv, N2D, Tv);
    }

    // 9. gate
    gate_kernel<<<(BTD + 255) / 256, 256>>>(p_Q, p_C, p_Y);

    // 10. out = Y @ Wo + bo + x
    {
        dim3 grid(Dv / 128, BT / 128);
        tgemm_kernel<2><<<grid, 256, SMEM_BYTES>>>(p_Y, Wo, bo, x, p_out, BT, Dv, Dv);
    }

    // 11. LN2
    ln_kernel<<<BT, 256>>>(p_out, ln2_g, ln2_b, p_h2);

    // 12. a1 = gelu(h2 @ W1 + b1)
    {
        dim3 grid(Hv / 128, BT / 128);
        tgemm_kernel<3><<<grid, 256, SMEM_BYTES>>>(p_h2, W1, b1, nullptr, p_a1, BT, Hv, Dv);
    }

    // 13. out = gelu(a1 @ W2 + b2) + out_residual
    {
        dim3 grid(Dv / 128, BT / 128);
        tgemm_kernel<4><<<grid, 256, SMEM_BYTES>>>(p_a1, W2, b2, p_out, out, BT, Dv, Hv);
    }
}

// round 3
// speedup vs baseline: 3.4160x; 1.0501x over previous
#include <cuda_runtime.h>
#include <math.h>
#include <stdint.h>

// Problem constants
constexpr int Bv = 8;
constexpr int Tv = 2048;
constexpr int Dv = 512;
constexpr int Hv = 2048;
constexpr int BT = Bv * Tv;            // 16384
constexpr int TD = Tv * Dv;            // 1048576
constexpr int BTD = Bv * Tv * Dv;      // 8388608
constexpr int N2D = Bv * 2 * Dv;       // 8192

// ---------------- scratch (device globals; no allocation allowed) ----------
__device__ float g_h   [BTD];          // LN1 out (tf32-rounded)
__device__ float g_K   [BTD];
__device__ float g_V   [BTD];
__device__ float g_Q   [BTD];
__device__ float g_Kmax[TD];
__device__ float g_expw[Tv * Tv];      // tf32-rounded
__device__ float g_U   [Tv * N2D];     // tf32-rounded
__device__ float g_C   [Tv * N2D];
__device__ float g_Y   [BTD];          // tf32-rounded
__device__ float g_out [BTD];
__device__ float g_h2  [BTD];          // LN2 out (tf32-rounded)
__device__ float g_a1  [BT * Hv];      // tf32-rounded
// tf32-rounded weight copies
__device__ float g_Wk[Dv * Dv];
__device__ float g_Wv[Dv * Dv];
__device__ float g_Wq[Dv * Dv];
__device__ float g_Wo[Dv * Dv];
__device__ float g_W1[Dv * Hv];
__device__ float g_W2[Hv * Dv];

__device__ __forceinline__ uint32_t f2tf(float f) {
    uint32_t r;
    asm("cvt.rna.tf32.f32 %0, %1;\n" : "=r"(r) : "f"(f));
    return r;
}
__device__ __forceinline__ float round_tf32(float f) {
    return __uint_as_float(f2tf(f));
}

// ---------------- weight pre-round: float4 vectorized ----------------
__global__ void round_w_kernel(const float* __restrict__ src,
                               float* __restrict__ dst, int n4) {
    int i = blockIdx.x * blockDim.x + threadIdx.x;
    if (i >= n4) return;
    float4 v = ((const float4*)src)[i];
    v.x = round_tf32(v.x); v.y = round_tf32(v.y);
    v.z = round_tf32(v.z); v.w = round_tf32(v.w);
    ((float4*)dst)[i] = v;
}

// ---------------- LayerNorm (output tf32-rounded) ----------------
__global__ void ln_kernel(const float* __restrict__ x,
                          const float* __restrict__ g,
                          const float* __restrict__ b,
                          float* __restrict__ y) {
    const int row = blockIdx.x;
    const float* xr = x + (size_t)row * Dv;
    const int t = threadIdx.x;
    float v0 = xr[t];
    float v1 = xr[t + 256];
    float s  = v0 + v1;
    float sq = v0 * v0 + v1 * v1;
    #pragma unroll
    for (int off = 16; off > 0; off >>= 1) {
        s  += __shfl_down_sync(0xffffffffu, s,  off);
        sq += __shfl_down_sync(0xffffffffu, sq, off);
    }
    __shared__ float ssum[8], ssq[8];
    __shared__ float s_mu, s_rstd;
    const int wid = t >> 5, lane = t & 31;
    if (lane == 0) { ssum[wid] = s; ssq[wid] = sq; }
    __syncthreads();
    if (t == 0) {
        float ts = 0.f, tq = 0.f;
        #pragma unroll
        for (int i = 0; i < 8; i++) { ts += ssum[i]; tq += ssq[i]; }
        float mu  = ts * (1.0f / Dv);
        float var = tq * (1.0f / Dv) - mu * mu;
        s_mu = mu;
        s_rstd = rsqrtf(var + 1e-5f);
    }
    __syncthreads();
    float* yr = y + (size_t)row * Dv;
    yr[t]       = round_tf32((v0 - s_mu) * s_rstd * g[t]       + b[t]);
    yr[t + 256] = round_tf32((v1 - s_mu) * s_rstd * g[t + 256] + b[t + 256]);
}

// ---------------- exp_w (output tf32-rounded) ----------------
__global__ void expw_kernel(const float* __restrict__ w, float* __restrict__ ew) {
    const int row = blockIdx.x;
    const float* wr = w + (size_t)row * Tv;
    const int t = threadIdx.x;
    float v[8];
    float m = -1e30f;
    #pragma unroll
    for (int i = 0; i < 8; i++) {
        v[i] = wr[t + i * 256];
        m = fmaxf(m, v[i]);
    }
    #pragma unroll
    for (int off = 16; off > 0; off >>= 1)
        m = fmaxf(m, __shfl_down_sync(0xffffffffu, m, off));
    __shared__ float sm[8];
    __shared__ float s_max;
    const int wid = t >> 5, lane = t & 31;
    if (lane == 0) sm[wid] = m;
    __syncthreads();
    if (t == 0) {
        float mm = sm[0];
        #pragma unroll
        for (int i = 1; i < 8; i++) mm = fmaxf(mm, sm[i]);
        s_max = mm;
    }
    __syncthreads();
    float* er = ew + (size_t)row * Tv;
    #pragma unroll
    for (int i = 0; i < 8; i++)
        er[t + i * 256] = round_tf32(expf(v[i] - s_max));
}

// ---------------- K batch-max ----------------
__global__ void kmax_kernel(const float* __restrict__ K, float* __restrict__ Kmax) {
    const int idx = blockIdx.x * blockDim.x + threadIdx.x;
    if (idx >= TD) return;
    float m = K[idx];
    #pragma unroll
    for (int b = 1; b < Bv; b++)
        m = fmaxf(m, K[(size_t)b * TD + idx]);
    Kmax[idx] = m;
}

// ---------------- build U (outputs tf32-rounded) ----------------
__global__ void buildU_kernel(const float* __restrict__ K,
                              const float* __restrict__ V,
                              const float* __restrict__ Kmax,
                              float* __restrict__ U) {
    const int idx = blockIdx.x * blockDim.x + threadIdx.x;
    if (idx >= BTD) return;
    const int b   = idx / TD;
    const int rem = idx - b * TD;
    const int s   = rem >> 9;
    const int d   = rem & 511;
    float e = expf(K[idx] - Kmax[rem]);
    size_t base = (size_t)s * N2D + b * 1024 + d;
    U[base]       = round_tf32(e);
    U[base + 512] = round_tf32(e * V[idx]);
}

// ---------------- gate (output tf32-rounded) ----------------
__global__ void gate_kernel(const float* __restrict__ Q,
                            const float* __restrict__ C,
                            float* __restrict__ Y) {
    const int idx = blockIdx.x * blockDim.x + threadIdx.x;
    if (idx >= BTD) return;
    const int b   = idx / TD;
    const int rem = idx - b * TD;
    const int t   = rem >> 9;
    const int d   = rem & 511;
    size_t base = (size_t)t * N2D + b * 1024 + d;
    float den = C[base];
    float num = C[base + 512];
    float q = Q[idx];
    float sig = 1.0f / (1.0f + expf(-q));
    Y[idx] = round_tf32(sig * num / den);
}

// ============================================================================
// TF32 tensor-core GEMM (operands pre-rounded; no cvt in mainloop)
// ============================================================================
__device__ __forceinline__ float gelu_exact(float v) {
    return 0.5f * v * (1.0f + erff(v * 0.70710678118654752f));
}

__device__ __forceinline__ void cp_async16(float* dst, const float* src) {
    uint32_t d = (uint32_t)__cvta_generic_to_shared(dst);
    asm volatile("cp.async.cg.shared.global [%0], [%1], 16;\n" :: "r"(d), "l"(src));
}
__device__ __forceinline__ void mma_tf32(float* c, const uint32_t* a, const uint32_t* b) {
    asm volatile(
        "mma.sync.aligned.m16n8k8.row.col.f32.tf32.tf32.f32 "
        "{%0,%1,%2,%3}, {%4,%5,%6,%7}, {%8,%9}, {%0,%1,%2,%3};\n"
        : "+f"(c[0]), "+f"(c[1]), "+f"(c[2]), "+f"(c[3])
        : "r"(a[0]), "r"(a[1]), "r"(a[2]), "r"(a[3]), "r"(b[0]), "r"(b[1]));
}

constexpr int BK = 32;
constexpr int AS_STRIDE = 36;
constexpr int BS_STRIDE = 136;
constexpr int AS_FLOATS = 128 * AS_STRIDE;
constexpr int BS_FLOATS = BK * BS_STRIDE;
constexpr int STAGE_FLOATS = AS_FLOATS + BS_FLOATS;
constexpr int SMEM_BYTES = 2 * STAGE_FLOATS * 4;      // 71680

// EPI: 0=none, 1=+bias, 2=+bias+res, 3=gelu(+bias)->round_tf32, 4=gelu(+bias)+res
template <int EPI>
__global__ __launch_bounds__(256, 2)
void tgemm_kernel(const float* __restrict__ A, const float* __restrict__ B,
                  const float* __restrict__ bias, const float* __restrict__ res,
                  float* __restrict__ C, int M, int N, int K) {
    extern __shared__ float smem[];
    const int tid  = threadIdx.x;
    const int lane = tid & 31;
    const int warp = tid >> 5;
    const int wrow = warp & 1;
    const int wcol = warp >> 1;
    const int bM = blockIdx.y * 128;
    const int bN = blockIdx.x * 128;

    float c[4][4][4];
    #pragma unroll
    for (int i = 0; i < 4; i++)
        #pragma unroll
        for (int j = 0; j < 4; j++)
            #pragma unroll
            for (int k = 0; k < 4; k++) c[i][j][k] = 0.f;

    const int nk = K / BK;

    auto load_stage = [&](int kt, int s) {
        float* As = smem + s * STAGE_FLOATS;
        float* Bs = As + AS_FLOATS;
        const float* Ag = A + (size_t)bM * K + kt * BK;
        const float* Bg = B + (size_t)(kt * BK) * N + bN;
        #pragma unroll
        for (int i = 0; i < 4; i++) {
            int ch = i * 256 + tid;
            int r  = ch >> 3;
            int cc = (ch & 7) * 4;
            cp_async16(As + r * AS_STRIDE + cc, Ag + (size_t)r * K + cc);
        }
        #pragma unroll
        for (int i = 0; i < 4; i++) {
            int ch = i * 256 + tid;
            int r  = ch >> 5;
            int cc = (ch & 31) * 4;
            cp_async16(Bs + r * BS_STRIDE + cc, Bg + (size_t)r * N + cc);
        }
        asm volatile("cp.async.commit_group;\n");
    };

    load_stage(0, 0);

    for (int kt = 0; kt < nk; kt++) {
        const int s = kt & 1;
        if (kt + 1 < nk) {
            load_stage(kt + 1, s ^ 1);
            asm volatile("cp.async.wait_group 1;\n");
        } else {
            asm volatile("cp.async.wait_group 0;\n");
        }
        __syncthreads();

        const uint32_t* As = (const uint32_t*)(smem + s * STAGE_FLOATS);
        const uint32_t* Bs = As + AS_FLOATS;

        #pragma unroll
        for (int ks = 0; ks < 4; ks++) {
            const int k = ks * 8 + (lane & 3);
            uint32_t a[4][4];
            #pragma unroll
            for (int mt = 0; mt < 4; mt++) {
                const int m = wrow * 64 + mt * 16 + (lane >> 2);
                a[mt][0] = As[m * AS_STRIDE + k];
                a[mt][1] = As[(m + 8) * AS_STRIDE + k];
                a[mt][2] = As[m * AS_STRIDE + k + 4];
                a[mt][3] = As[(m + 8) * AS_STRIDE + k + 4];
            }
            uint32_t b[4][2];
            #pragma unroll
            for (int nt = 0; nt < 4; nt++) {
                const int n = wcol * 32 + nt * 8 + (lane >> 2);
                b[nt][0] = Bs[k * BS_STRIDE + n];
                b[nt][1] = Bs[(k + 4) * BS_STRIDE + n];
            }
            #pragma unroll
            for (int mt = 0; mt < 4; mt++)
                #pragma unroll
                for (int nt = 0; nt < 4; nt++)
                    mma_tf32(c[mt][nt], a[mt], b[nt]);
        }
        __syncthreads();
    }

    #pragma unroll
    for (int mt = 0; mt < 4; mt++) {
        #pragma unroll
        for (int nt = 0; nt < 4; nt++) {
            const int row0 = bM + wrow * 64 + mt * 16 + (lane >> 2);
            const int col  = bN + wcol * 32 + nt * 8 + (lane & 3) * 2;
            #pragma unroll
            for (int h = 0; h < 2; h++) {
                const size_t row = row0 + h * 8;
                float v0 = c[mt][nt][h * 2 + 0];
                float v1 = c[mt][nt][h * 2 + 1];
                if (EPI >= 1) { v0 += bias[col]; v1 += bias[col + 1]; }
                if (EPI == 3 || EPI == 4) { v0 = gelu_exact(v0); v1 = gelu_exact(v1); }
                if (EPI == 3) { v0 = round_tf32(v0); v1 = round_tf32(v1); }
                if (EPI == 2 || EPI == 4) {
                    v0 += res[row * N + col];
                    v1 += res[row * N + col + 1];
                }
                *(float2*)(C + row * N + col) = make_float2(v0, v1);
            }
        }
    }
}

// ---------------- launch ----------------
extern "C" void kernel_launch(void* const* d_in, const int* in_sizes, int n_in,
                              void* d_out, int out_size) {
    const float* x     = (const float*)d_in[0];
    const float* ln1_g = (const float*)d_in[1];
    const float* ln1_b = (const float*)d_in[2];
    const float* Wk    = (const float*)d_in[3];
    const float* bk    = (const float*)d_in[4];
    const float* Wv    = (const float*)d_in[5];
    const float* bv    = (const float*)d_in[6];
    const float* Wq    = (const float*)d_in[7];
    const float* bq    = (const float*)d_in[8];
    const float* w     = (const float*)d_in[9];
    const float* Wo    = (const float*)d_in[10];
    const float* bo    = (const float*)d_in[11];
    const float* ln2_g = (const float*)d_in[12];
    const float* ln2_b = (const float*)d_in[13];
    const float* W1    = (const float*)d_in[14];
    const float* b1    = (const float*)d_in[15];
    const float* W2    = (const float*)d_in[16];
    const float* b2    = (const float*)d_in[17];
    float* out = (float*)d_out;

    float *p_h, *p_K, *p_V, *p_Q, *p_Kmax, *p_expw, *p_U, *p_C, *p_Y,
          *p_out, *p_h2, *p_a1;
    float *p_Wk, *p_Wv, *p_Wq, *p_Wo, *p_W1, *p_W2;
    cudaGetSymbolAddress((void**)&p_h,    g_h);
    cudaGetSymbolAddress((void**)&p_K,    g_K);
    cudaGetSymbolAddress((void**)&p_V,    g_V);
    cudaGetSymbolAddress((void**)&p_Q,    g_Q);
    cudaGetSymbolAddress((void**)&p_Kmax, g_Kmax);
    cudaGetSymbolAddress((void**)&p_expw, g_expw);
    cudaGetSymbolAddress((void**)&p_U,    g_U);
    cudaGetSymbolAddress((void**)&p_C,    g_C);
    cudaGetSymbolAddress((void**)&p_Y,    g_Y);
    cudaGetSymbolAddress((void**)&p_out,  g_out);
    cudaGetSymbolAddress((void**)&p_h2,   g_h2);
    cudaGetSymbolAddress((void**)&p_a1,   g_a1);
    cudaGetSymbolAddress((void**)&p_Wk,   g_Wk);
    cudaGetSymbolAddress((void**)&p_Wv,   g_Wv);
    cudaGetSymbolAddress((void**)&p_Wq,   g_Wq);
    cudaGetSymbolAddress((void**)&p_Wo,   g_Wo);
    cudaGetSymbolAddress((void**)&p_W1,   g_W1);
    cudaGetSymbolAddress((void**)&p_W2,   g_W2);

    cudaFuncSetAttribute(tgemm_kernel<0>, cudaFuncAttributeMaxDynamicSharedMemorySize, SMEM_BYTES);
    cudaFuncSetAttribute(tgemm_kernel<1>, cudaFuncAttributeMaxDynamicSharedMemorySize, SMEM_BYTES);
    cudaFuncSetAttribute(tgemm_kernel<2>, cudaFuncAttributeMaxDynamicSharedMemorySize, SMEM_BYTES);
    cudaFuncSetAttribute(tgemm_kernel<3>, cudaFuncAttributeMaxDynamicSharedMemorySize, SMEM_BYTES);
    cudaFuncSetAttribute(tgemm_kernel<4>, cudaFuncAttributeMaxDynamicSharedMemorySize, SMEM_BYTES);

    // 0. pre-round weights to tf32
    {
        const int TPB = 256;
        round_w_kernel<<<(Dv * Dv / 4 + TPB - 1) / TPB, TPB>>>(Wk, p_Wk, Dv * Dv / 4);
        round_w_kernel<<<(Dv * Dv / 4 + TPB - 1) / TPB, TPB>>>(Wv, p_Wv, Dv * Dv / 4);
        round_w_kernel<<<(Dv * Dv / 4 + TPB - 1) / TPB, TPB>>>(Wq, p_Wq, Dv * Dv / 4);
        round_w_kernel<<<(Dv * Dv / 4 + TPB - 1) / TPB, TPB>>>(Wo, p_Wo, Dv * Dv / 4);
        round_w_kernel<<<(Dv * Hv / 4 + TPB - 1) / TPB, TPB>>>(W1, p_W1, Dv * Hv / 4);
        round_w_kernel<<<(Hv * Dv / 4 + TPB - 1) / TPB, TPB>>>(W2, p_W2, Hv * Dv / 4);
    }

    // 1. LN1 (rounded out)
    ln_kernel<<<BT, 256>>>(x, ln1_g, ln1_b, p_h);

    // 2-4. K, V, Q projections
    {
        dim3 grid(Dv / 128, BT / 128);
        tgemm_kernel<1><<<grid, 256, SMEM_BYTES>>>(p_h, p_Wk, bk, nullptr, p_K, BT, Dv, Dv);
        tgemm_kernel<1><<<grid, 256, SMEM_BYTES>>>(p_h, p_Wv, bv, nullptr, p_V, BT, Dv, Dv);
        tgemm_kernel<1><<<grid, 256, SMEM_BYTES>>>(p_h, p_Wq, bq, nullptr, p_Q, BT, Dv, Dv);
    }

    // 5. batch-max of K
    kmax_kernel<<<(TD + 255) / 256, 256>>>(p_K, p_Kmax);

    // 6. exp_w
    expw_kernel<<<Tv, 256>>>(w, p_expw);

    // 7. build U
    buildU_kernel<<<(BTD + 255) / 256, 256>>>(p_K, p_V, p_Kmax, p_U);

    // 8. AFT core GEMM
    {
        dim3 grid(N2D / 128, Tv / 128);
        tgemm_kernel<0><<<grid, 256, SMEM_BYTES>>>(p_expw, p_U, nullptr, nullptr, p_C, Tv, N2D, Tv);
    }

    // 9. gate
    gate_kernel<<<(BTD + 255) / 256, 256>>>(p_Q, p_C, p_Y);

    // 10. out = Y @ Wo + bo + x
    {
        dim3 grid(Dv / 128, BT / 128);
        tgemm_kernel<2><<<grid, 256, SMEM_BYTES>>>(p_Y, p_Wo, bo, x, p_out, BT, Dv, Dv);
    }

    // 11. LN2 (rounded out)
    ln_kernel<<<BT, 256>>>(p_out, ln2_g, ln2_b, p_h2);

    // 12. a1 = gelu(h2 @ W1 + b1), rounded out
    {
        dim3 grid(Hv / 128, BT / 128);
        tgemm_kernel<3><<<grid, 256, SMEM_BYTES>>>(p_h2, p_W1, b1, nullptr, p_a1, BT, Hv, Dv);
    }

    // 13. out = gelu(a1 @ W2 + b2) + out_residual
    {
        dim3 grid(Dv / 128, BT / 128);
        tgemm_kernel<4><<<grid, 256, SMEM_BYTES>>>(p_a1, p_W2, b2, p_out, out, BT, Dv, Hv);
    }
}

// round 4
// speedup vs baseline: 6.4354x; 1.8839x over previous
#include <cuda_runtime.h>
#include <cuda_fp16.h>
#include <math.h>
#include <stdint.h>

// Problem constants
constexpr int Bv = 8;
constexpr int Tv = 2048;
constexpr int Dv = 512;
constexpr int Hv = 2048;
constexpr int BT = Bv * Tv;            // 16384
constexpr int TD = Tv * Dv;            // 1048576
constexpr int BTD = Bv * Tv * Dv;      // 8388608
constexpr int N2D = Bv * 2 * Dv;       // 8192
constexpr int NKVQ = 3 * Dv;           // 1536

// ---------------- scratch (device globals) ----------------
__device__ __half g_h   [BTD];                 // LN1 out
__device__ float  g_KVQ [(size_t)BT * NKVQ];   // K|V|Q fused, fp32
__device__ float  g_Kmax[TD];
__device__ __half g_expw[Tv * Tv];
__device__ __half g_U   [(size_t)Tv * N2D];
__device__ float  g_C   [(size_t)Tv * N2D];
__device__ __half g_Y   [BTD];
__device__ float  g_out [BTD];
__device__ __half g_h2  [BTD];
__device__ __half g_a1  [(size_t)BT * Hv];
// half weight copies
__device__ __half g_Wkvq[Dv * NKVQ];
__device__ float  g_bkvq[NKVQ];
__device__ __half g_Wo  [Dv * Dv];
__device__ __half g_W1  [Dv * Hv];
__device__ __half g_W2  [Hv * Dv];

// ---------------- weight fp32 -> fp16 ----------------
__global__ void w2h_kernel(const float* __restrict__ src,
                           __half* __restrict__ dst, int n4) {
    int i = blockIdx.x * blockDim.x + threadIdx.x;
    if (i >= n4) return;
    float4 v = ((const float4*)src)[i];
    ((__half2*)dst)[i * 2 + 0] = __floats2half2_rn(v.x, v.y);
    ((__half2*)dst)[i * 2 + 1] = __floats2half2_rn(v.z, v.w);
}

// pack Wk|Wv|Wq -> [512][1536] half
__global__ void kvqpack_kernel(const float* __restrict__ Wk,
                               const float* __restrict__ Wv,
                               const float* __restrict__ Wq,
                               __half* __restrict__ dst) {
    int idx = blockIdx.x * blockDim.x + threadIdx.x;
    if (idx >= Dv * NKVQ) return;
    int d = idx / NKVQ;
    int j = idx - d * NKVQ;
    float v;
    if (j < 512)       v = Wk[d * 512 + j];
    else if (j < 1024) v = Wv[d * 512 + j - 512];
    else               v = Wq[d * 512 + j - 1024];
    dst[idx] = __float2half_rn(v);
}
__global__ void bpack_kernel(const float* __restrict__ bk,
                             const float* __restrict__ bv,
                             const float* __restrict__ bq,
                             float* __restrict__ dst) {
    int j = blockIdx.x * blockDim.x + threadIdx.x;
    if (j >= NKVQ) return;
    dst[j] = (j < 512) ? bk[j] : (j < 1024) ? bv[j - 512] : bq[j - 1024];
}

// ---------------- LayerNorm (half out) ----------------
__global__ void ln_kernel(const float* __restrict__ x,
                          const float* __restrict__ g,
                          const float* __restrict__ b,
                          __half* __restrict__ y) {
    const int row = blockIdx.x;
    const float* xr = x + (size_t)row * Dv;
    const int t = threadIdx.x;
    float v0 = xr[t];
    float v1 = xr[t + 256];
    float s  = v0 + v1;
    float sq = v0 * v0 + v1 * v1;
    #pragma unroll
    for (int off = 16; off > 0; off >>= 1) {
        s  += __shfl_down_sync(0xffffffffu, s,  off);
        sq += __shfl_down_sync(0xffffffffu, sq, off);
    }
    __shared__ float ssum[8], ssq[8];
    __shared__ float s_mu, s_rstd;
    const int wid = t >> 5, lane = t & 31;
    if (lane == 0) { ssum[wid] = s; ssq[wid] = sq; }
    __syncthreads();
    if (t == 0) {
        float ts = 0.f, tq = 0.f;
        #pragma unroll
        for (int i = 0; i < 8; i++) { ts += ssum[i]; tq += ssq[i]; }
        float mu  = ts * (1.0f / Dv);
        float var = tq * (1.0f / Dv) - mu * mu;
        s_mu = mu;
        s_rstd = rsqrtf(var + 1e-5f);
    }
    __syncthreads();
    __half* yr = y + (size_t)row * Dv;
    yr[t]       = __float2half_rn((v0 - s_mu) * s_rstd * g[t]       + b[t]);
    yr[t + 256] = __float2half_rn((v1 - s_mu) * s_rstd * g[t + 256] + b[t + 256]);
}

// ---------------- exp_w (half out) ----------------
__global__ void expw_kernel(const float* __restrict__ w, __half* __restrict__ ew) {
    const int row = blockIdx.x;
    const float* wr = w + (size_t)row * Tv;
    const int t = threadIdx.x;
    float v[8];
    float m = -1e30f;
    #pragma unroll
    for (int i = 0; i < 8; i++) {
        v[i] = wr[t + i * 256];
        m = fmaxf(m, v[i]);
    }
    #pragma unroll
    for (int off = 16; off > 0; off >>= 1)
        m = fmaxf(m, __shfl_down_sync(0xffffffffu, m, off));
    __shared__ float sm[8];
    __shared__ float s_max;
    const int wid = t >> 5, lane = t & 31;
    if (lane == 0) sm[wid] = m;
    __syncthreads();
    if (t == 0) {
        float mm = sm[0];
        #pragma unroll
        for (int i = 1; i < 8; i++) mm = fmaxf(mm, sm[i]);
        s_max = mm;
    }
    __syncthreads();
    __half* er = ew + (size_t)row * Tv;
    #pragma unroll
    for (int i = 0; i < 8; i++)
        er[t + i * 256] = __float2half_rn(expf(v[i] - s_max));
}

// ---------------- K batch-max (K = cols 0..511 of KVQ) ----------------
__global__ void kmax_kernel(const float* __restrict__ KVQ, float* __restrict__ Kmax) {
    const int idx = blockIdx.x * blockDim.x + threadIdx.x;
    if (idx >= TD) return;
    const int t = idx >> 9;
    const int d = idx & 511;
    float m = -1e30f;
    #pragma unroll
    for (int b = 0; b < Bv; b++)
        m = fmaxf(m, KVQ[((size_t)(b * Tv + t)) * NKVQ + d]);
    Kmax[idx] = m;
}

// ---------------- build U (half out) ----------------
__global__ void buildU_kernel(const float* __restrict__ KVQ,
                              const float* __restrict__ Kmax,
                              __half* __restrict__ U) {
    const int idx = blockIdx.x * blockDim.x + threadIdx.x;
    if (idx >= BTD) return;
    const int b   = idx / TD;
    const int rem = idx - b * TD;
    const int s   = rem >> 9;
    const int d   = rem & 511;
    size_t rbase = ((size_t)(b * Tv + s)) * NKVQ;
    float K = KVQ[rbase + d];
    float V = KVQ[rbase + 512 + d];
    float e = expf(K - Kmax[rem]);
    size_t base = (size_t)s * N2D + b * 1024 + d;
    U[base]       = __float2half_rn(e);
    U[base + 512] = __float2half_rn(e * V);
}

// ---------------- gate (half out) ----------------
__global__ void gate_kernel(const float* __restrict__ KVQ,
                            const float* __restrict__ C,
                            __half* __restrict__ Y) {
    const int idx = blockIdx.x * blockDim.x + threadIdx.x;
    if (idx >= BTD) return;
    const int b   = idx / TD;
    const int rem = idx - b * TD;
    const int t   = rem >> 9;
    const int d   = rem & 511;
    size_t base = (size_t)t * N2D + b * 1024 + d;
    float den = C[base];
    float num = C[base + 512];
    float q = KVQ[((size_t)(b * Tv + t)) * NKVQ + 1024 + d];
    float sig = 1.0f / (1.0f + expf(-q));
    Y[idx] = __float2half_rn(sig * num / den);
}

// ============================================================================
// FP16 tensor-core GEMM: 128x128x32 tile, 256 thr, 3-stage cp.async, ldmatrix
// ============================================================================
__device__ __forceinline__ float gelu_exact(float v) {
    return 0.5f * v * (1.0f + erff(v * 0.70710678118654752f));
}
__device__ __forceinline__ void cp_async16h(__half* dst, const __half* src) {
    uint32_t d = (uint32_t)__cvta_generic_to_shared(dst);
    asm volatile("cp.async.cg.shared.global [%0], [%1], 16;\n" :: "r"(d), "l"(src));
}
__device__ __forceinline__ void ldsm4(uint32_t* r, uint32_t addr) {
    asm volatile("ldmatrix.sync.aligned.m8n8.x4.shared.b16 {%0,%1,%2,%3}, [%4];"
        : "=r"(r[0]), "=r"(r[1]), "=r"(r[2]), "=r"(r[3]) : "r"(addr));
}
__device__ __forceinline__ void ldsm4t(uint32_t* r, uint32_t addr) {
    asm volatile("ldmatrix.sync.aligned.m8n8.x4.trans.shared.b16 {%0,%1,%2,%3}, [%4];"
        : "=r"(r[0]), "=r"(r[1]), "=r"(r[2]), "=r"(r[3]) : "r"(addr));
}
__device__ __forceinline__ void mma_f16(float* c, const uint32_t* a, const uint32_t* b) {
    asm volatile(
        "mma.sync.aligned.m16n8k16.row.col.f32.f16.f16.f32 "
        "{%0,%1,%2,%3}, {%4,%5,%6,%7}, {%8,%9}, {%0,%1,%2,%3};\n"
        : "+f"(c[0]), "+f"(c[1]), "+f"(c[2]), "+f"(c[3])
        : "r"(a[0]), "r"(a[1]), "r"(a[2]), "r"(a[3]), "r"(b[0]), "r"(b[1]));
}

constexpr int BK = 32;
constexpr int A_HALVES = 128 * BK;             // 4096 halves, 8KB
constexpr int B_HALVES = BK * 128;             // 4096 halves, 8KB
constexpr int STAGE_HALVES = A_HALVES + B_HALVES;
constexpr int NSTAGE = 3;
constexpr int SMEM_BYTES = NSTAGE * STAGE_HALVES * 2;  // 49152

// EPI: 0=none(f32), 1=+bias(f32), 2=+bias+res(f32), 3=gelu(+bias)->half,
//      4=gelu(+bias)+res(f32)
template <int EPI>
__global__ __launch_bounds__(256, 2)
void hgemm_kernel(const __half* __restrict__ A, const __half* __restrict__ B,
                  const float* __restrict__ bias, const float* __restrict__ res,
                  void* __restrict__ Cout, int M, int N, int K) {
    extern __shared__ __half sm[];
    const int tid  = threadIdx.x;
    const int lane = tid & 31;
    const int warp = tid >> 5;
    const int wrow = warp & 1;     // 2 x 64 rows
    const int wcol = warp >> 1;    // 4 x 32 cols
    const int bM = blockIdx.y * 128;
    const int bN = blockIdx.x * 128;
    const int lane15 = lane & 15;
    const int lanehi = lane >> 4;

    float c[4][4][4];
    #pragma unroll
    for (int i = 0; i < 4; i++)
        #pragma unroll
        for (int j = 0; j < 4; j++)
            #pragma unroll
            for (int k = 0; k < 4; k++) c[i][j][k] = 0.f;

    const int nk = K / BK;

    auto load_stage = [&](int kt, int s) {
        __half* As = sm + s * STAGE_HALVES;
        __half* Bs = As + A_HALVES;
        const __half* Ag = A + (size_t)bM * K + kt * BK;
        const __half* Bg = B + (size_t)(kt * BK) * N + bN;
        #pragma unroll
        for (int i = 0; i < 2; i++) {            // A: 512 16B chunks
            int ch = i * 256 + tid;
            int r = ch >> 2, cc = ch & 3;
            int pc = cc ^ ((r >> 1) & 3);
            cp_async16h(As + r * 32 + pc * 8, Ag + (size_t)r * K + cc * 8);
        }
        #pragma unroll
        for (int i = 0; i < 2; i++) {            // B: 512 16B chunks
            int ch = i * 256 + tid;
            int k = ch >> 4, cc = ch & 15;
            int pc = cc ^ (k & 7);
            cp_async16h(Bs + k * 128 + pc * 8, Bg + (size_t)k * N + cc * 8);
        }
        asm volatile("cp.async.commit_group;\n");
    };

    load_stage(0, 0);
    load_stage(1, 1);
    load_stage(2, 2);

    for (int kt = 0; kt < nk; kt++) {
        asm volatile("cp.async.wait_group 2;\n");
        __syncthreads();

        const __half* As = sm + (kt % 3) * STAGE_HALVES;
        uint32_t a_base = (uint32_t)__cvta_generic_to_shared(As);
        uint32_t b_base = a_base + A_HALVES * 2;

        #pragma unroll
        for (int k16 = 0; k16 < 2; k16++) {
            uint32_t a[4][4];
            #pragma unroll
            for (int mt = 0; mt < 4; mt++) {
                int r = wrow * 64 + mt * 16 + lane15;
                int cc = 2 * k16 + lanehi;
                int pc = cc ^ ((r >> 1) & 3);
                ldsm4(a[mt], a_base + (r * 32 + pc * 8) * 2);
            }
            uint32_t b[2][4];
            #pragma unroll
            for (int nt2 = 0; nt2 < 2; nt2++) {
                int kr = k16 * 16 + lane15;
                int cc = wcol * 4 + nt2 * 2 + lanehi;
                int pc = cc ^ (kr & 7);
                ldsm4t(b[nt2], b_base + (kr * 128 + pc * 8) * 2);
            }
            #pragma unroll
            for (int mt = 0; mt < 4; mt++)
                #pragma unroll
                for (int nt = 0; nt < 4; nt++)
                    mma_f16(c[mt][nt], a[mt], &b[nt >> 1][(nt & 1) * 2]);
        }
        __syncthreads();
        if (kt + 3 < nk) load_stage(kt + 3, (kt + 3) % 3);
        else asm volatile("cp.async.commit_group;\n");
    }

    // epilogue
    #pragma unroll
    for (int mt = 0; mt < 4; mt++) {
        #pragma unroll
        for (int nt = 0; nt < 4; nt++) {
            const int row0 = bM + wrow * 64 + mt * 16 + (lane >> 2);
            const int col  = bN + wcol * 32 + nt * 8 + (lane & 3) * 2;
            #pragma unroll
            for (int h = 0; h < 2; h++) {
                const size_t row = row0 + h * 8;
                float v0 = c[mt][nt][h * 2 + 0];
                float v1 = c[mt][nt][h * 2 + 1];
                if (EPI >= 1) { v0 += bias[col]; v1 += bias[col + 1]; }
                if (EPI == 3 || EPI == 4) { v0 = gelu_exact(v0); v1 = gelu_exact(v1); }
                if (EPI == 2 || EPI == 4) {
                    v0 += res[row * N + col];
                    v1 += res[row * N + col + 1];
                }
                if (EPI == 3) {
                    *(__half2*)((__half*)Cout + row * N + col) =
                        __floats2half2_rn(v0, v1);
                } else {
                    *(float2*)((float*)Cout + row * N + col) = make_float2(v0, v1);
                }
            }
        }
    }
}

// ---------------- launch ----------------
extern "C" void kernel_launch(void* const* d_in, const int* in_sizes, int n_in,
                              void* d_out, int out_size) {
    const float* x     = (const float*)d_in[0];
    const float* ln1_g = (const float*)d_in[1];
    const float* ln1_b = (const float*)d_in[2];
    const float* Wk    = (const float*)d_in[3];
    const float* bk    = (const float*)d_in[4];
    const float* Wv    = (const float*)d_in[5];
    const float* bv    = (const float*)d_in[6];
    const float* Wq    = (const float*)d_in[7];
    const float* bq    = (const float*)d_in[8];
    const float* w     = (const float*)d_in[9];
    const float* Wo    = (const float*)d_in[10];
    const float* bo    = (const float*)d_in[11];
    const float* ln2_g = (const float*)d_in[12];
    const float* ln2_b = (const float*)d_in[13];
    const float* W1    = (const float*)d_in[14];
    const float* b1    = (const float*)d_in[15];
    const float* W2    = (const float*)d_in[16];
    const float* b2    = (const float*)d_in[17];
    float* out = (float*)d_out;

    __half *p_h, *p_expw, *p_U, *p_Y, *p_h2, *p_a1, *p_Wkvq, *p_Wo, *p_W1, *p_W2;
    float *p_KVQ, *p_Kmax, *p_C, *p_out, *p_bkvq;
    cudaGetSymbolAddress((void**)&p_h,    g_h);
    cudaGetSymbolAddress((void**)&p_KVQ,  g_KVQ);
    cudaGetSymbolAddress((void**)&p_Kmax, g_Kmax);
    cudaGetSymbolAddress((void**)&p_expw, g_expw);
    cudaGetSymbolAddress((void**)&p_U,    g_U);
    cudaGetSymbolAddress((void**)&p_C,    g_C);
    cudaGetSymbolAddress((void**)&p_Y,    g_Y);
    cudaGetSymbolAddress((void**)&p_out,  g_out);
    cudaGetSymbolAddress((void**)&p_h2,   g_h2);
    cudaGetSymbolAddress((void**)&p_a1,   g_a1);
    cudaGetSymbolAddress((void**)&p_Wkvq, g_Wkvq);
    cudaGetSymbolAddress((void**)&p_bkvq, g_bkvq);
    cudaGetSymbolAddress((void**)&p_Wo,   g_Wo);
    cudaGetSymbolAddress((void**)&p_W1,   g_W1);
    cudaGetSymbolAddress((void**)&p_W2,   g_W2);

    cudaFuncSetAttribute(hgemm_kernel<0>, cudaFuncAttributeMaxDynamicSharedMemorySize, SMEM_BYTES);
    cudaFuncSetAttribute(hgemm_kernel<1>, cudaFuncAttributeMaxDynamicSharedMemorySize, SMEM_BYTES);
    cudaFuncSetAttribute(hgemm_kernel<2>, cudaFuncAttributeMaxDynamicSharedMemorySize, SMEM_BYTES);
    cudaFuncSetAttribute(hgemm_kernel<3>, cudaFuncAttributeMaxDynamicSharedMemorySize, SMEM_BYTES);
    cudaFuncSetAttribute(hgemm_kernel<4>, cudaFuncAttributeMaxDynamicSharedMemorySize, SMEM_BYTES);

    const int TPB = 256;
    // 0. weight conversions
    kvqpack_kernel<<<(Dv * NKVQ + TPB - 1) / TPB, TPB>>>(Wk, Wv, Wq, p_Wkvq);
    bpack_kernel<<<(NKVQ + TPB - 1) / TPB, TPB>>>(bk, bv, bq, p_bkvq);
    w2h_kernel<<<(Dv * Dv / 4 + TPB - 1) / TPB, TPB>>>(Wo, p_Wo, Dv * Dv / 4);
    w2h_kernel<<<(Dv * Hv / 4 + TPB - 1) / TPB, TPB>>>(W1, p_W1, Dv * Hv / 4);
    w2h_kernel<<<(Hv * Dv / 4 + TPB - 1) / TPB, TPB>>>(W2, p_W2, Hv * Dv / 4);

    // 1. LN1
    ln_kernel<<<BT, 256>>>(x, ln1_g, ln1_b, p_h);

    // 2. fused KVQ projection: [16384,512] @ [512,1536]
    {
        dim3 grid(NKVQ / 128, BT / 128);
        hgemm_kernel<1><<<grid, 256, SMEM_BYTES>>>(p_h, p_Wkvq, p_bkvq, nullptr,
                                                   p_KVQ, BT, NKVQ, Dv);
    }

    // 3. batch-max of K
    kmax_kernel<<<(TD + 255) / 256, 256>>>(p_KVQ, p_Kmax);

    // 4. exp_w
    expw_kernel<<<Tv, 256>>>(w, p_expw);

    // 5. build U
    buildU_kernel<<<(BTD + 255) / 256, 256>>>(p_KVQ, p_Kmax, p_U);

    // 6. AFT core GEMM: C[2048, 8192] = expw @ U, K=2048
    {
        dim3 grid(N2D / 128, Tv / 128);
        hgemm_kernel<0><<<grid, 256, SMEM_BYTES>>>(p_expw, p_U, nullptr, nullptr,
                                                   p_C, Tv, N2D, Tv);
    }

    // 7. gate
    gate_kernel<<<(BTD + 255) / 256, 256>>>(p_KVQ, p_C, p_Y);

    // 8. out = Y @ Wo + bo + x
    {
        dim3 grid(Dv / 128, BT / 128);
        hgemm_kernel<2><<<grid, 256, SMEM_BYTES>>>(p_Y, p_Wo, bo, x,
                                                   p_out, BT, Dv, Dv);
    }

    // 9. LN2
    ln_kernel<<<BT, 256>>>(p_out, ln2_g, ln2_b, p_h2);

    // 10. a1 = gelu(h2 @ W1 + b1) -> half
    {
        dim3 grid(Hv / 128, BT / 128);
        hgemm_kernel<3><<<grid, 256, SMEM_BYTES>>>(p_h2, p_W1, b1, nullptr,
                                                   p_a1, BT, Hv, Dv);
    }

    // 11. out = gelu(a1 @ W2 + b2) + out_residual
    {
        dim3 grid(Dv / 128, BT / 128);
        hgemm_kernel<4><<<grid, 256, SMEM_BYTES>>>(p_a1, p_W2, b2, p_out,
                                                   out, BT, Dv, Hv);
    }
}